// round 1
// baseline (speedup 1.0000x reference)
#include <cuda_runtime.h>
#include <math.h>

// Problem shape (fixed by the dataset)
constexpr int B_  = 8;
constexpr int S_  = 2048;
constexpr int D_  = 1024;
constexpr int DK_ = 128;   // == DV
constexpr int H_  = 4096;  // 4*D
constexpr int R_  = B_ * S_;   // 16384 rows

// ---------------------------------------------------------------------------
// Scratch (device globals -- no dynamic allocation allowed)
// ---------------------------------------------------------------------------
__device__ float g_xn [R_ * D_];        //  64 MB  ln1(x)
__device__ float g_q  [R_ * DK_];       //   8 MB
__device__ float g_k  [R_ * DK_];       //   8 MB
__device__ float g_v  [R_ * DK_];       //   8 MB
__device__ float g_sc [B_ * S_ * S_];   // 128 MB  attention scores
__device__ float g_ho [R_ * DK_];       //   8 MB  attention output
__device__ float g_y  [R_ * D_];        //  64 MB  post-attn residual
__device__ float g_h  [R_ * D_];        //  64 MB  ln2(y)
__device__ float g_mid[R_ * H_];        // 256 MB  MLP hidden

// ---------------------------------------------------------------------------
// LayerNorm: one block per row, D=1024 -> 256 threads x float4
// ---------------------------------------------------------------------------
__global__ __launch_bounds__(256)
void ln_kernel(const float* __restrict__ x, const float* __restrict__ g,
               const float* __restrict__ b, float* __restrict__ out)
{
    int row = blockIdx.x;
    int t = threadIdx.x;
    float4 v = reinterpret_cast<const float4*>(x + (size_t)row * D_)[t];
    float s  = v.x + v.y + v.z + v.w;
    float ss = v.x*v.x + v.y*v.y + v.z*v.z + v.w*v.w;
    #pragma unroll
    for (int o = 16; o > 0; o >>= 1) {
        s  += __shfl_xor_sync(0xffffffffu, s,  o);
        ss += __shfl_xor_sync(0xffffffffu, ss, o);
    }
    __shared__ float rs[8], rss[8];
    if ((t & 31) == 0) { rs[t >> 5] = s; rss[t >> 5] = ss; }
    __syncthreads();
    float sum = 0.f, sumsq = 0.f;
    #pragma unroll
    for (int i = 0; i < 8; i++) { sum += rs[i]; sumsq += rss[i]; }
    float mu   = sum * (1.0f / D_);
    float var  = sumsq * (1.0f / D_) - mu * mu;
    float rstd = rsqrtf(var + 1e-5f);
    float4 gg = reinterpret_cast<const float4*>(g)[t];
    float4 bb = reinterpret_cast<const float4*>(b)[t];
    float4 o;
    o.x = (v.x - mu) * rstd * gg.x + bb.x;
    o.y = (v.y - mu) * rstd * gg.y + bb.y;
    o.z = (v.z - mu) * rstd * gg.z + bb.z;
    o.w = (v.w - mu) * rstd * gg.w + bb.w;
    reinterpret_cast<float4*>(out + (size_t)row * D_)[t] = o;
}

// ---------------------------------------------------------------------------
// Row softmax over S_=2048: one block per row, 256 threads x 8 elems
// ---------------------------------------------------------------------------
__global__ __launch_bounds__(256)
void softmax_kernel(float* __restrict__ sc)
{
    float* p = sc + (size_t)blockIdx.x * S_;
    int t = threadIdx.x;
    float4 a = reinterpret_cast<float4*>(p)[t];
    float4 b = reinterpret_cast<float4*>(p)[t + 256];
    float m = fmaxf(fmaxf(fmaxf(a.x, a.y), fmaxf(a.z, a.w)),
                    fmaxf(fmaxf(b.x, b.y), fmaxf(b.z, b.w)));
    #pragma unroll
    for (int o = 16; o > 0; o >>= 1) m = fmaxf(m, __shfl_xor_sync(0xffffffffu, m, o));
    __shared__ float rm[8], rsm[8];
    if ((t & 31) == 0) rm[t >> 5] = m;
    __syncthreads();
    m = rm[0];
    #pragma unroll
    for (int i = 1; i < 8; i++) m = fmaxf(m, rm[i]);

    a.x = __expf(a.x - m); a.y = __expf(a.y - m);
    a.z = __expf(a.z - m); a.w = __expf(a.w - m);
    b.x = __expf(b.x - m); b.y = __expf(b.y - m);
    b.z = __expf(b.z - m); b.w = __expf(b.w - m);
    float s = a.x + a.y + a.z + a.w + b.x + b.y + b.z + b.w;
    #pragma unroll
    for (int o = 16; o > 0; o >>= 1) s += __shfl_xor_sync(0xffffffffu, s, o);
    if ((t & 31) == 0) rsm[t >> 5] = s;
    __syncthreads();
    s = 0.f;
    #pragma unroll
    for (int i = 0; i < 8; i++) s += rsm[i];
    float inv = 1.0f / s;
    a.x *= inv; a.y *= inv; a.z *= inv; a.w *= inv;
    b.x *= inv; b.y *= inv; b.z *= inv; b.w *= inv;
    reinterpret_cast<float4*>(p)[t]       = a;
    reinterpret_cast<float4*>(p)[t + 256] = b;
}

// ---------------------------------------------------------------------------
// Tiled SGEMM: C[M,N] = A[M,K] @ B (NN: B[K,N] | NT: B[N,K]^T) , batched via z.
// 128x128x16 tile, 256 threads, 8x8 microtile.
// EPI: 0 none | 1 +bias | 2 gelu(+bias) | 3 +bias+res | 4 *alpha
// ---------------------------------------------------------------------------
constexpr int BM = 128, BN = 128, BK = 16;

template<int EPI, bool NT>
__global__ __launch_bounds__(256)
void gemm_kernel(const float* __restrict__ A, const float* __restrict__ Bm,
                 const float* __restrict__ bias, const float* __restrict__ res,
                 float* __restrict__ C, int M, int N, int K,
                 size_t batchA, size_t batchB, size_t batchC, float alpha)
{
    __shared__ float tA[BK][BM];
    __shared__ float tB[BK][BN];

    const float* Ab = A + blockIdx.z * batchA + (size_t)(blockIdx.y * BM) * K;
    const float* Bb = NT ? Bm + blockIdx.z * batchB + (size_t)(blockIdx.x * BN) * K
                         : Bm + blockIdx.z * batchB + blockIdx.x * BN;
    float*       Cb = C + blockIdx.z * batchC + (size_t)(blockIdx.y * BM) * N + blockIdx.x * BN;
    const float* Rb = (EPI == 3)
        ? res + blockIdx.z * batchC + (size_t)(blockIdx.y * BM) * N + blockIdx.x * BN
        : nullptr;

    int tid = threadIdx.x;
    int tx = tid & 15, ty = tid >> 4;

    float acc[8][8];
    #pragma unroll
    for (int i = 0; i < 8; i++)
        #pragma unroll
        for (int j = 0; j < 8; j++) acc[i][j] = 0.f;

    for (int k0 = 0; k0 < K; k0 += BK) {
        // A tile: 128 rows x 16 cols (transposed into smem)
        #pragma unroll
        for (int i = 0; i < 2; i++) {
            int r = (tid >> 2) + i * 64;
            int c = (tid & 3) << 2;
            float4 a4 = *reinterpret_cast<const float4*>(Ab + (size_t)r * K + k0 + c);
            tA[c + 0][r] = a4.x; tA[c + 1][r] = a4.y;
            tA[c + 2][r] = a4.z; tA[c + 3][r] = a4.w;
        }
        if (NT) {
            // B tile from B[N,K]: 128 n-rows x 16 k-cols, transposed into smem
            #pragma unroll
            for (int i = 0; i < 2; i++) {
                int n = (tid >> 2) + i * 64;
                int c = (tid & 3) << 2;
                float4 b4 = *reinterpret_cast<const float4*>(Bb + (size_t)n * K + k0 + c);
                tB[c + 0][n] = b4.x; tB[c + 1][n] = b4.y;
                tB[c + 2][n] = b4.z; tB[c + 3][n] = b4.w;
            }
        } else {
            // B tile from B[K,N]: 16 k-rows x 128 n-cols, direct
            #pragma unroll
            for (int i = 0; i < 2; i++) {
                int r = (tid >> 5) + i * 8;
                int c = (tid & 31) << 2;
                *reinterpret_cast<float4*>(&tB[r][c]) =
                    *reinterpret_cast<const float4*>(Bb + (size_t)(k0 + r) * N + c);
            }
        }
        __syncthreads();
        #pragma unroll
        for (int k = 0; k < BK; k++) {
            float ra[8], rb[8];
            #pragma unroll
            for (int i = 0; i < 8; i++) ra[i] = tA[k][ty * 8 + i];
            #pragma unroll
            for (int j = 0; j < 8; j++) rb[j] = tB[k][tx * 8 + j];
            #pragma unroll
            for (int i = 0; i < 8; i++)
                #pragma unroll
                for (int j = 0; j < 8; j++)
                    acc[i][j] = fmaf(ra[i], rb[j], acc[i][j]);
        }
        __syncthreads();
    }

    float bcol[8];
    if (EPI == 1 || EPI == 2 || EPI == 3) {
        #pragma unroll
        for (int j = 0; j < 8; j++) bcol[j] = bias[blockIdx.x * BN + tx * 8 + j];
    }
    #pragma unroll
    for (int i = 0; i < 8; i++) {
        int r = ty * 8 + i;
        #pragma unroll
        for (int j = 0; j < 8; j++) {
            float v = acc[i][j];
            if (EPI == 4) v *= alpha;
            if (EPI == 1 || EPI == 2 || EPI == 3) v += bcol[j];
            if (EPI == 2) v = 0.5f * v * (1.0f + erff(v * 0.70710678118654752f));
            if (EPI == 3) v += Rb[(size_t)r * N + tx * 8 + j];
            Cb[(size_t)r * N + tx * 8 + j] = v;
        }
    }
}

// ---------------------------------------------------------------------------
// Launch graph
// ---------------------------------------------------------------------------
extern "C" void kernel_launch(void* const* d_in, const int* in_sizes, int n_in,
                              void* d_out, int out_size)
{
    (void)in_sizes; (void)n_in; (void)out_size;
    const float* x    = (const float*)d_in[0];
    const float* ln1g = (const float*)d_in[1];
    const float* ln1b = (const float*)d_in[2];
    const float* Wq   = (const float*)d_in[3];
    const float* bq   = (const float*)d_in[4];
    const float* Wk   = (const float*)d_in[5];
    const float* bk   = (const float*)d_in[6];
    const float* Wv   = (const float*)d_in[7];
    const float* bv   = (const float*)d_in[8];
    const float* Wo   = (const float*)d_in[9];
    const float* bo   = (const float*)d_in[10];
    const float* ln2g = (const float*)d_in[11];
    const float* ln2b = (const float*)d_in[12];
    const float* W1   = (const float*)d_in[13];
    const float* b1   = (const float*)d_in[14];
    const float* W2   = (const float*)d_in[15];
    const float* b2   = (const float*)d_in[16];
    float* out = (float*)d_out;

    float *xn, *q, *k, *v, *sc, *ho, *y, *h, *mid;
    cudaGetSymbolAddress((void**)&xn,  g_xn);
    cudaGetSymbolAddress((void**)&q,   g_q);
    cudaGetSymbolAddress((void**)&k,   g_k);
    cudaGetSymbolAddress((void**)&v,   g_v);
    cudaGetSymbolAddress((void**)&sc,  g_sc);
    cudaGetSymbolAddress((void**)&ho,  g_ho);
    cudaGetSymbolAddress((void**)&y,   g_y);
    cudaGetSymbolAddress((void**)&h,   g_h);
    cudaGetSymbolAddress((void**)&mid, g_mid);

    const float scale = 0.08838834764831845f;  // 1/sqrt(128)

    // 1. xn = LN1(x)
    ln_kernel<<<R_, 256>>>(x, ln1g, ln1b, xn);

    // 2-4. q/k/v = xn @ W{q,k,v} + b   [16384,1024]x[1024,128]
    gemm_kernel<1, false><<<dim3(1, 128, 1), 256>>>(xn, Wq, bq, nullptr, q, R_, DK_, D_, 0, 0, 0, 0.f);
    gemm_kernel<1, false><<<dim3(1, 128, 1), 256>>>(xn, Wk, bk, nullptr, k, R_, DK_, D_, 0, 0, 0, 0.f);
    gemm_kernel<1, false><<<dim3(1, 128, 1), 256>>>(xn, Wv, bv, nullptr, v, R_, DK_, D_, 0, 0, 0, 0.f);

    // 5. sc[b] = q[b] @ k[b]^T * scale   batched [2048,2048,128]
    gemm_kernel<4, true><<<dim3(16, 16, B_), 256>>>(
        q, k, nullptr, nullptr, sc, S_, S_, DK_,
        (size_t)S_ * DK_, (size_t)S_ * DK_, (size_t)S_ * S_, scale);

    // 6. softmax rows
    softmax_kernel<<<R_, 256>>>(sc);

    // 7. ho[b] = sc[b] @ v[b]   batched [2048,128,2048]
    gemm_kernel<0, false><<<dim3(1, 16, B_), 256>>>(
        sc, v, nullptr, nullptr, ho, S_, DK_, S_,
        (size_t)S_ * S_, (size_t)S_ * DK_, (size_t)S_ * DK_, 0.f);

    // 8. y = xn + ho @ Wo + bo   [16384,128]x[128,1024]
    gemm_kernel<3, false><<<dim3(8, 128, 1), 256>>>(ho, Wo, bo, xn, y, R_, D_, DK_, 0, 0, 0, 0.f);

    // 9. h = LN2(y)
    ln_kernel<<<R_, 256>>>(y, ln2g, ln2b, h);

    // 10. mid = gelu(h @ W1 + b1)   [16384,1024]x[1024,4096]
    gemm_kernel<2, false><<<dim3(32, 128, 1), 256>>>(h, W1, b1, nullptr, mid, R_, H_, D_, 0, 0, 0, 0.f);

    // 11. out = y + mid @ W2 + b2   [16384,4096]x[4096,1024]
    gemm_kernel<3, false><<<dim3(8, 128, 1), 256>>>(mid, W2, b2, y, out, R_, D_, H_, 0, 0, 0, 0.f);
}

// round 6
// speedup vs baseline: 2.2498x; 2.2498x over previous
#include <cuda_runtime.h>
#include <math.h>
#include <stdint.h>

// Problem shape (fixed by the dataset)
constexpr int B_  = 8;
constexpr int S_  = 2048;
constexpr int D_  = 1024;
constexpr int DK_ = 128;   // == DV
constexpr int H_  = 4096;  // 4*D
constexpr int R_  = B_ * S_;   // 16384 rows

// ---------------------------------------------------------------------------
// Scratch (device globals -- no dynamic allocation allowed)
// ---------------------------------------------------------------------------
__device__ float g_xn [R_ * D_];              //  64 MB  ln1(x)
__device__ float g_q  [R_ * DK_];             //   8 MB
__device__ float g_k  [R_ * DK_];             //   8 MB
__device__ float g_kt [R_ * DK_];             //   8 MB  k^T per batch [b][DK][S]
__device__ float g_v  [R_ * DK_];             //   8 MB
__device__ float g_sc [(size_t)B_ * S_ * S_]; // 134 MB  attention scores
__device__ float g_ho [R_ * DK_];             //   8 MB  attention output
__device__ float g_y  [R_ * D_];              //  64 MB  post-attn residual
__device__ float g_h  [R_ * D_];              //  64 MB  ln2(y)
__device__ float g_mid[(size_t)R_ * H_];      // 268 MB  MLP hidden

// ---------------------------------------------------------------------------
// helpers
// ---------------------------------------------------------------------------
__device__ __forceinline__ uint32_t smem_u32(const void* p) {
    uint32_t a;
    asm("{ .reg .u64 t; cvta.to.shared.u64 t, %1; cvt.u32.u64 %0, t; }"
        : "=r"(a) : "l"(p));
    return a;
}
__device__ __forceinline__ uint32_t f2tf(float x) {
    uint32_t r;
    asm("cvt.rn.tf32.f32 %0, %1;" : "=r"(r) : "f"(x));
    return r;
}
__device__ __forceinline__ void cpasync16(uint32_t dst, const float* src) {
    asm volatile("cp.async.cg.shared.global [%0], [%1], 16;" :: "r"(dst), "l"(src));
}
__device__ __forceinline__ void mma8(float* c, const uint32_t* a, const uint32_t* b) {
    asm volatile(
        "mma.sync.aligned.m16n8k8.row.col.f32.tf32.tf32.f32 "
        "{%0,%1,%2,%3},{%4,%5,%6,%7},{%8,%9},{%0,%1,%2,%3};"
        : "+f"(c[0]), "+f"(c[1]), "+f"(c[2]), "+f"(c[3])
        : "r"(a[0]), "r"(a[1]), "r"(a[2]), "r"(a[3]), "r"(b[0]), "r"(b[1]));
}

// ---------------------------------------------------------------------------
// LayerNorm: one block per row, D=1024 -> 256 threads x float4
// ---------------------------------------------------------------------------
__global__ __launch_bounds__(256)
void ln_kernel(const float* __restrict__ x, const float* __restrict__ g,
               const float* __restrict__ b, float* __restrict__ out)
{
    int row = blockIdx.x;
    int t = threadIdx.x;
    float4 v = reinterpret_cast<const float4*>(x + (size_t)row * D_)[t];
    float s  = v.x + v.y + v.z + v.w;
    float ss = v.x*v.x + v.y*v.y + v.z*v.z + v.w*v.w;
    #pragma unroll
    for (int o = 16; o > 0; o >>= 1) {
        s  += __shfl_xor_sync(0xffffffffu, s,  o);
        ss += __shfl_xor_sync(0xffffffffu, ss, o);
    }
    __shared__ float rs[8], rss[8];
    if ((t & 31) == 0) { rs[t >> 5] = s; rss[t >> 5] = ss; }
    __syncthreads();
    float sum = 0.f, sumsq = 0.f;
    #pragma unroll
    for (int i = 0; i < 8; i++) { sum += rs[i]; sumsq += rss[i]; }
    float mu   = sum * (1.0f / D_);
    float var  = sumsq * (1.0f / D_) - mu * mu;
    float rstd = rsqrtf(var + 1e-5f);
    float4 gg = reinterpret_cast<const float4*>(g)[t];
    float4 bb = reinterpret_cast<const float4*>(b)[t];
    float4 o;
    o.x = (v.x - mu) * rstd * gg.x + bb.x;
    o.y = (v.y - mu) * rstd * gg.y + bb.y;
    o.z = (v.z - mu) * rstd * gg.z + bb.z;
    o.w = (v.w - mu) * rstd * gg.w + bb.w;
    reinterpret_cast<float4*>(out + (size_t)row * D_)[t] = o;
}

// ---------------------------------------------------------------------------
// Row softmax over S_=2048: one block per row, 256 threads x 8 elems
// ---------------------------------------------------------------------------
__global__ __launch_bounds__(256)
void softmax_kernel(float* __restrict__ sc)
{
    float* p = sc + (size_t)blockIdx.x * S_;
    int t = threadIdx.x;
    float4 a = reinterpret_cast<float4*>(p)[t];
    float4 b = reinterpret_cast<float4*>(p)[t + 256];
    float m = fmaxf(fmaxf(fmaxf(a.x, a.y), fmaxf(a.z, a.w)),
                    fmaxf(fmaxf(b.x, b.y), fmaxf(b.z, b.w)));
    #pragma unroll
    for (int o = 16; o > 0; o >>= 1) m = fmaxf(m, __shfl_xor_sync(0xffffffffu, m, o));
    __shared__ float rm[8], rsm[8];
    if ((t & 31) == 0) rm[t >> 5] = m;
    __syncthreads();
    m = rm[0];
    #pragma unroll
    for (int i = 1; i < 8; i++) m = fmaxf(m, rm[i]);

    a.x = __expf(a.x - m); a.y = __expf(a.y - m);
    a.z = __expf(a.z - m); a.w = __expf(a.w - m);
    b.x = __expf(b.x - m); b.y = __expf(b.y - m);
    b.z = __expf(b.z - m); b.w = __expf(b.w - m);
    float s = a.x + a.y + a.z + a.w + b.x + b.y + b.z + b.w;
    #pragma unroll
    for (int o = 16; o > 0; o >>= 1) s += __shfl_xor_sync(0xffffffffu, s, o);
    if ((t & 31) == 0) rsm[t >> 5] = s;
    __syncthreads();
    s = 0.f;
    #pragma unroll
    for (int i = 0; i < 8; i++) s += rsm[i];
    float inv = 1.0f / s;
    a.x *= inv; a.y *= inv; a.z *= inv; a.w *= inv;
    b.x *= inv; b.y *= inv; b.z *= inv; b.w *= inv;
    reinterpret_cast<float4*>(p)[t]       = a;
    reinterpret_cast<float4*>(p)[t + 256] = b;
}

// ---------------------------------------------------------------------------
// Batched 32x32 transpose: in[z][Rr][Cc] -> out[z][Cc][Rr]
// ---------------------------------------------------------------------------
__global__ __launch_bounds__(256)
void transpose_batched(const float* __restrict__ in, float* __restrict__ out,
                       int Rr, int Cc)
{
    __shared__ float t[32][33];
    size_t base = (size_t)blockIdx.z * Rr * Cc;
    int bx = blockIdx.x * 32;   // column offset in `in`
    int by = blockIdx.y * 32;   // row offset in `in`
    int x = threadIdx.x, y = threadIdx.y;  // 32x8
    #pragma unroll
    for (int i = 0; i < 32; i += 8)
        t[y + i][x] = in[base + (size_t)(by + y + i) * Cc + bx + x];
    __syncthreads();
    #pragma unroll
    for (int i = 0; i < 32; i += 8)
        out[base + (size_t)(bx + y + i) * Rr + by + x] = t[x][y + i];
}

// ---------------------------------------------------------------------------
// tf32 mma.sync GEMM:  C[M,N] = A[M,K] @ B[K,N]  (all NN, batched via z)
// 128x128x32 CTA tile, 256 threads = 8 warps (2m x 4n), warp tile 64x32.
// Double-buffered cp.async.  Fragments tf32-rounded with cvt.rn.tf32.
// EPI: 0 none | 1 +bias | 2 +bias+gelu | 3 +bias+residual | 4 *alpha
// ---------------------------------------------------------------------------
constexpr int SM_A   = 128 * 36 * 4;            // 18432 B per A buffer
constexpr int SM_B   = 32 * 136 * 4;            // 17408 B per B buffer
constexpr int SM_TOT = 2 * SM_A + 2 * SM_B;     // 71680 B

template<int EPI>
__global__ __launch_bounds__(256)
void gemm_mma(const float* __restrict__ A, const float* __restrict__ Bm,
              const float* __restrict__ bias, const float* __restrict__ res,
              float* __restrict__ C, int M, int N, int K,
              size_t bA, size_t bB, size_t bC, float alpha)
{
    extern __shared__ char smem[];
    float* AsBuf[2] = { (float*)smem, (float*)(smem + SM_A) };
    float* BsBuf[2] = { (float*)(smem + 2 * SM_A), (float*)(smem + 2 * SM_A + SM_B) };

    const int tid = threadIdx.x;
    const int wid = tid >> 5, lane = tid & 31;
    const int wm = wid >> 2, wn = wid & 3;      // 2 x 4 warp grid
    const int g = lane >> 2, tq = lane & 3;     // groupID / threadInGroup
    const int mb = blockIdx.y * 128, nb = blockIdx.x * 128;

    const float* Ab = A  + blockIdx.z * bA + (size_t)mb * K;
    const float* Bb = Bm + blockIdx.z * bB + nb;
    float*       Cb = C  + blockIdx.z * bC;
    const float* Rb = (EPI == 3) ? res + blockIdx.z * bC : nullptr;

    // cp.async source/dest mapping
    const int ar = tid >> 1, ak = (tid & 1) * 16;   // A: row 0..127, k-offset 0/16
    const int br = tid >> 3, bc = tid & 7;          // B: k-row 0..31, n-slot
    uint32_t sm0 = smem_u32(smem);
    uint32_t a_dst0 = sm0 + (uint32_t)(ar * 36 + ak) * 4;
    uint32_t b_dst0 = sm0 + 2 * SM_A + (uint32_t)(br * 136 + bc * 4) * 4;
    const float* a_src = Ab + (size_t)ar * K + ak;
    const float* b_src = Bb + (size_t)br * N + bc * 4;

    auto load = [&](int c, int buf) {
        uint32_t ad = a_dst0 + buf * SM_A;
        uint32_t bd = b_dst0 + buf * SM_B;
        const float* as = a_src + c * 32;
        const float* bs = b_src + (size_t)c * 32 * N;
        #pragma unroll
        for (int j = 0; j < 4; j++) cpasync16(ad + j * 16, as + j * 4);
        #pragma unroll
        for (int j = 0; j < 4; j++) cpasync16(bd + j * 128, bs + j * 32);
        asm volatile("cp.async.commit_group;" ::: "memory");
    };

    float acc[4][4][4];
    #pragma unroll
    for (int i = 0; i < 4; i++)
        #pragma unroll
        for (int j = 0; j < 4; j++)
            #pragma unroll
            for (int r = 0; r < 4; r++) acc[i][j][r] = 0.f;

    const int NC = K / 32;   // >= 4 for every GEMM in this graph
    load(0, 0);
    load(1, 1);

    for (int c = 0; c < NC; c++) {
        if (c + 1 < NC) asm volatile("cp.async.wait_group 1;" ::: "memory");
        else            asm volatile("cp.async.wait_group 0;" ::: "memory");
        __syncthreads();

        const int buf = c & 1;
        const float* As_ = AsBuf[buf];
        const float* Bs_ = BsBuf[buf];
        #pragma unroll
        for (int ks = 0; ks < 4; ks++) {
            const int kk = ks * 8;
            uint32_t af[4][4], bf[4][2];
            #pragma unroll
            for (int i = 0; i < 4; i++) {
                const float* p = As_ + (wm * 64 + i * 16 + g) * 36 + kk + tq;
                af[i][0] = f2tf(p[0]);
                af[i][1] = f2tf(p[8 * 36]);
                af[i][2] = f2tf(p[4]);
                af[i][3] = f2tf(p[8 * 36 + 4]);
            }
            #pragma unroll
            for (int j = 0; j < 4; j++) {
                const float* p = Bs_ + (kk + tq) * 136 + wn * 32 + j * 8 + g;
                bf[j][0] = f2tf(p[0]);
                bf[j][1] = f2tf(p[4 * 136]);
            }
            #pragma unroll
            for (int i = 0; i < 4; i++)
                #pragma unroll
                for (int j = 0; j < 4; j++)
                    mma8(acc[i][j], af[i], bf[j]);
        }
        __syncthreads();
        if (c + 2 < NC) load(c + 2, buf);
    }

    // epilogue: thread owns rows (r0, r0+8), cols (col, col+1) per (i,j)
    #pragma unroll
    for (int i = 0; i < 4; i++) {
        const int r0 = mb + wm * 64 + i * 16 + g;
        #pragma unroll
        for (int j = 0; j < 4; j++) {
            const int col = nb + wn * 32 + j * 8 + 2 * tq;
            float v0 = acc[i][j][0], v1 = acc[i][j][1];
            float v2 = acc[i][j][2], v3 = acc[i][j][3];
            if (EPI == 4) { v0 *= alpha; v1 *= alpha; v2 *= alpha; v3 *= alpha; }
            if (EPI == 1 || EPI == 2 || EPI == 3) {
                float2 bb = *reinterpret_cast<const float2*>(bias + col);
                v0 += bb.x; v1 += bb.y; v2 += bb.x; v3 += bb.y;
            }
            if (EPI == 2) {
                v0 = 0.5f * v0 * (1.0f + erff(v0 * 0.70710678118654752f));
                v1 = 0.5f * v1 * (1.0f + erff(v1 * 0.70710678118654752f));
                v2 = 0.5f * v2 * (1.0f + erff(v2 * 0.70710678118654752f));
                v3 = 0.5f * v3 * (1.0f + erff(v3 * 0.70710678118654752f));
            }
            if (EPI == 3) {
                float2 r1 = *reinterpret_cast<const float2*>(Rb + (size_t)r0 * N + col);
                float2 r2 = *reinterpret_cast<const float2*>(Rb + (size_t)(r0 + 8) * N + col);
                v0 += r1.x; v1 += r1.y; v2 += r2.x; v3 += r2.y;
            }
            *reinterpret_cast<float2*>(Cb + (size_t)r0 * N + col)       = make_float2(v0, v1);
            *reinterpret_cast<float2*>(Cb + (size_t)(r0 + 8) * N + col) = make_float2(v2, v3);
        }
    }
}

// ---------------------------------------------------------------------------
// Launch graph
// ---------------------------------------------------------------------------
extern "C" void kernel_launch(void* const* d_in, const int* in_sizes, int n_in,
                              void* d_out, int out_size)
{
    (void)in_sizes; (void)n_in; (void)out_size;
    const float* x    = (const float*)d_in[0];
    const float* ln1g = (const float*)d_in[1];
    const float* ln1b = (const float*)d_in[2];
    const float* Wq   = (const float*)d_in[3];
    const float* bq   = (const float*)d_in[4];
    const float* Wk   = (const float*)d_in[5];
    const float* bk   = (const float*)d_in[6];
    const float* Wv   = (const float*)d_in[7];
    const float* bv   = (const float*)d_in[8];
    const float* Wo   = (const float*)d_in[9];
    const float* bo   = (const float*)d_in[10];
    const float* ln2g = (const float*)d_in[11];
    const float* ln2b = (const float*)d_in[12];
    const float* W1   = (const float*)d_in[13];
    const float* b1   = (const float*)d_in[14];
    const float* W2   = (const float*)d_in[15];
    const float* b2   = (const float*)d_in[16];
    float* out = (float*)d_out;

    float *xn, *q, *k, *kt, *v, *sc, *ho, *y, *h, *mid;
    cudaGetSymbolAddress((void**)&xn,  g_xn);
    cudaGetSymbolAddress((void**)&q,   g_q);
    cudaGetSymbolAddress((void**)&k,   g_k);
    cudaGetSymbolAddress((void**)&kt,  g_kt);
    cudaGetSymbolAddress((void**)&v,   g_v);
    cudaGetSymbolAddress((void**)&sc,  g_sc);
    cudaGetSymbolAddress((void**)&ho,  g_ho);
    cudaGetSymbolAddress((void**)&y,   g_y);
    cudaGetSymbolAddress((void**)&h,   g_h);
    cudaGetSymbolAddress((void**)&mid, g_mid);

    cudaFuncSetAttribute(gemm_mma<0>, cudaFuncAttributeMaxDynamicSharedMemorySize, SM_TOT);
    cudaFuncSetAttribute(gemm_mma<1>, cudaFuncAttributeMaxDynamicSharedMemorySize, SM_TOT);
    cudaFuncSetAttribute(gemm_mma<2>, cudaFuncAttributeMaxDynamicSharedMemorySize, SM_TOT);
    cudaFuncSetAttribute(gemm_mma<3>, cudaFuncAttributeMaxDynamicSharedMemorySize, SM_TOT);
    cudaFuncSetAttribute(gemm_mma<4>, cudaFuncAttributeMaxDynamicSharedMemorySize, SM_TOT);

    const float scale = 0.08838834764831845f;  // 1/sqrt(128)

    // 1. xn = LN1(x)
    ln_kernel<<<R_, 256>>>(x, ln1g, ln1b, xn);

    // 2-4. q/k/v = xn @ W{q,k,v} + b   [16384,1024]x[1024,128]
    gemm_mma<1><<<dim3(1, 128, 1), 256, SM_TOT>>>(xn, Wq, bq, nullptr, q, R_, DK_, D_, 0, 0, 0, 0.f);
    gemm_mma<1><<<dim3(1, 128, 1), 256, SM_TOT>>>(xn, Wk, bk, nullptr, k, R_, DK_, D_, 0, 0, 0, 0.f);
    gemm_mma<1><<<dim3(1, 128, 1), 256, SM_TOT>>>(xn, Wv, bv, nullptr, v, R_, DK_, D_, 0, 0, 0, 0.f);

    // 4b. kt[b] = k[b]^T   ([S,DK] -> [DK,S] per batch)
    transpose_batched<<<dim3(DK_ / 32, S_ / 32, B_), dim3(32, 8)>>>(k, kt, S_, DK_);

    // 5. sc[b] = q[b] @ kt[b] * scale   batched [2048,2048] K=128
    gemm_mma<4><<<dim3(16, 16, B_), 256, SM_TOT>>>(
        q, kt, nullptr, nullptr, sc, S_, S_, DK_,
        (size_t)S_ * DK_, (size_t)DK_ * S_, (size_t)S_ * S_, scale);

    // 6. softmax rows
    softmax_kernel<<<R_, 256>>>(sc);

    // 7. ho[b] = sc[b] @ v[b]   batched [2048,128] K=2048
    gemm_mma<0><<<dim3(1, 16, B_), 256, SM_TOT>>>(
        sc, v, nullptr, nullptr, ho, S_, DK_, S_,
        (size_t)S_ * S_, (size_t)S_ * DK_, (size_t)S_ * DK_, 0.f);

    // 8. y = xn + ho @ Wo + bo   [16384,128]x[128,1024]
    gemm_mma<3><<<dim3(8, 128, 1), 256, SM_TOT>>>(ho, Wo, bo, xn, y, R_, D_, DK_, 0, 0, 0, 0.f);

    // 9. h = LN2(y)
    ln_kernel<<<R_, 256>>>(y, ln2g, ln2b, h);

    // 10. mid = gelu(h @ W1 + b1)   [16384,1024]x[1024,4096]
    gemm_mma<2><<<dim3(32, 128, 1), 256, SM_TOT>>>(h, W1, b1, nullptr, mid, R_, H_, D_, 0, 0, 0, 0.f);

    // 11. out = y + mid @ W2 + b2   [16384,4096]x[4096,1024]
    gemm_mma<3><<<dim3(8, 128, 1), 256, SM_TOT>>>(mid, W2, b2, y, out, R_, D_, H_, 0, 0, 0, 0.f);
}

// round 7
// speedup vs baseline: 5.3233x; 2.3661x over previous
#include <cuda_runtime.h>
#include <cuda_fp16.h>
#include <math.h>
#include <stdint.h>

// Problem shape (fixed by the dataset)
constexpr int B_  = 8;
constexpr int S_  = 2048;
constexpr int D_  = 1024;
constexpr int DK_ = 128;   // == DV
constexpr int H_  = 4096;  // 4*D
constexpr int R_  = B_ * S_;   // 16384 rows

// ---------------------------------------------------------------------------
// Scratch (device globals -- no dynamic allocation allowed)
// ---------------------------------------------------------------------------
__device__ float  g_xn [R_ * D_];              // fp32 ln1(x)  (residual source)
__device__ __half g_xnh[R_ * D_];              // fp16 ln1(x)  (GEMM A)
__device__ __half g_qh [R_ * DK_];
__device__ __half g_kh [R_ * DK_];
__device__ __half g_kth[R_ * DK_];             // k^T per batch [b][DK][S]
__device__ __half g_vh [R_ * DK_];
__device__ float  g_sc [(size_t)B_ * S_ * S_]; // fp32 attention scores
__device__ __half g_sch[(size_t)B_ * S_ * S_]; // fp16 softmax probs
__device__ __half g_hoh[R_ * DK_];             // fp16 attention output
__device__ float  g_y  [R_ * D_];              // fp32 post-attn residual
__device__ __half g_hh [R_ * D_];              // fp16 ln2(y)
__device__ __half g_midh[(size_t)R_ * H_];     // fp16 MLP hidden
// fp16 weights
__device__ __half g_wqh[D_ * DK_];
__device__ __half g_wkh[D_ * DK_];
__device__ __half g_wvh[D_ * DK_];
__device__ __half g_woh[DK_ * D_];
__device__ __half g_w1h[(size_t)D_ * H_];
__device__ __half g_w2h[(size_t)H_ * D_];

// ---------------------------------------------------------------------------
// helpers
// ---------------------------------------------------------------------------
__device__ __forceinline__ uint32_t smem_u32(const void* p) {
    uint32_t a;
    asm("{ .reg .u64 t; cvta.to.shared.u64 t, %1; cvt.u32.u64 %0, t; }"
        : "=r"(a) : "l"(p));
    return a;
}
__device__ __forceinline__ void cpasync16(uint32_t dst, const void* src) {
    asm volatile("cp.async.cg.shared.global [%0], [%1], 16;" :: "r"(dst), "l"(src));
}
__device__ __forceinline__ void ldm_x4(uint32_t* r, uint32_t addr) {
    asm volatile("ldmatrix.sync.aligned.m8n8.x4.shared.b16 {%0,%1,%2,%3}, [%4];"
        : "=r"(r[0]), "=r"(r[1]), "=r"(r[2]), "=r"(r[3]) : "r"(addr));
}
__device__ __forceinline__ void ldm_x4_t(uint32_t* r, uint32_t addr) {
    asm volatile("ldmatrix.sync.aligned.m8n8.x4.trans.shared.b16 {%0,%1,%2,%3}, [%4];"
        : "=r"(r[0]), "=r"(r[1]), "=r"(r[2]), "=r"(r[3]) : "r"(addr));
}
__device__ __forceinline__ void mma16(float* c, const uint32_t* a, const uint32_t* b) {
    asm volatile(
        "mma.sync.aligned.m16n8k16.row.col.f32.f16.f16.f32 "
        "{%0,%1,%2,%3},{%4,%5,%6,%7},{%8,%9},{%0,%1,%2,%3};"
        : "+f"(c[0]), "+f"(c[1]), "+f"(c[2]), "+f"(c[3])
        : "r"(a[0]), "r"(a[1]), "r"(a[2]), "r"(a[3]), "r"(b[0]), "r"(b[1]));
}
__device__ __forceinline__ void store2(float* p, float a, float b) {
    *reinterpret_cast<float2*>(p) = make_float2(a, b);
}
__device__ __forceinline__ void store2(__half* p, float a, float b) {
    *reinterpret_cast<__half2*>(p) = __floats2half2_rn(a, b);
}

// ---------------------------------------------------------------------------
// fp32 -> fp16 elementwise (n % 4 == 0)
// ---------------------------------------------------------------------------
__global__ __launch_bounds__(256)
void f2h_kernel(const float* __restrict__ in, __half* __restrict__ out, int n4)
{
    int i = blockIdx.x * blockDim.x + threadIdx.x;
    if (i < n4) {
        float4 v = reinterpret_cast<const float4*>(in)[i];
        reinterpret_cast<__half2*>(out)[2 * i]     = __floats2half2_rn(v.x, v.y);
        reinterpret_cast<__half2*>(out)[2 * i + 1] = __floats2half2_rn(v.z, v.w);
    }
}

// ---------------------------------------------------------------------------
// LayerNorm: one block per row, D=1024 -> 256 threads x float4
// W32: write fp32 out32 ; W16: write fp16 out16
// ---------------------------------------------------------------------------
template<bool W32, bool W16>
__global__ __launch_bounds__(256)
void ln_kernel(const float* __restrict__ x, const float* __restrict__ g,
               const float* __restrict__ b, float* __restrict__ out32,
               __half* __restrict__ out16)
{
    int row = blockIdx.x;
    int t = threadIdx.x;
    float4 v = reinterpret_cast<const float4*>(x + (size_t)row * D_)[t];
    float s  = v.x + v.y + v.z + v.w;
    float ss = v.x*v.x + v.y*v.y + v.z*v.z + v.w*v.w;
    #pragma unroll
    for (int o = 16; o > 0; o >>= 1) {
        s  += __shfl_xor_sync(0xffffffffu, s,  o);
        ss += __shfl_xor_sync(0xffffffffu, ss, o);
    }
    __shared__ float rs[8], rss[8];
    if ((t & 31) == 0) { rs[t >> 5] = s; rss[t >> 5] = ss; }
    __syncthreads();
    float sum = 0.f, sumsq = 0.f;
    #pragma unroll
    for (int i = 0; i < 8; i++) { sum += rs[i]; sumsq += rss[i]; }
    float mu   = sum * (1.0f / D_);
    float var  = sumsq * (1.0f / D_) - mu * mu;
    float rstd = rsqrtf(var + 1e-5f);
    float4 gg = reinterpret_cast<const float4*>(g)[t];
    float4 bb = reinterpret_cast<const float4*>(b)[t];
    float4 o;
    o.x = (v.x - mu) * rstd * gg.x + bb.x;
    o.y = (v.y - mu) * rstd * gg.y + bb.y;
    o.z = (v.z - mu) * rstd * gg.z + bb.z;
    o.w = (v.w - mu) * rstd * gg.w + bb.w;
    if (W32)
        reinterpret_cast<float4*>(out32 + (size_t)row * D_)[t] = o;
    if (W16) {
        __half2* p = reinterpret_cast<__half2*>(out16 + (size_t)row * D_);
        p[2 * t]     = __floats2half2_rn(o.x, o.y);
        p[2 * t + 1] = __floats2half2_rn(o.z, o.w);
    }
}

// ---------------------------------------------------------------------------
// Row softmax over S_=2048: fp32 in, fp16 out
// ---------------------------------------------------------------------------
__global__ __launch_bounds__(256)
void softmax_kernel(const float* __restrict__ sc, __half* __restrict__ out)
{
    const float* p = sc + (size_t)blockIdx.x * S_;
    __half2* q = reinterpret_cast<__half2*>(out + (size_t)blockIdx.x * S_);
    int t = threadIdx.x;
    float4 a = reinterpret_cast<const float4*>(p)[t];
    float4 b = reinterpret_cast<const float4*>(p)[t + 256];
    float m = fmaxf(fmaxf(fmaxf(a.x, a.y), fmaxf(a.z, a.w)),
                    fmaxf(fmaxf(b.x, b.y), fmaxf(b.z, b.w)));
    #pragma unroll
    for (int o = 16; o > 0; o >>= 1) m = fmaxf(m, __shfl_xor_sync(0xffffffffu, m, o));
    __shared__ float rm[8], rsm[8];
    if ((t & 31) == 0) rm[t >> 5] = m;
    __syncthreads();
    m = rm[0];
    #pragma unroll
    for (int i = 1; i < 8; i++) m = fmaxf(m, rm[i]);

    a.x = __expf(a.x - m); a.y = __expf(a.y - m);
    a.z = __expf(a.z - m); a.w = __expf(a.w - m);
    b.x = __expf(b.x - m); b.y = __expf(b.y - m);
    b.z = __expf(b.z - m); b.w = __expf(b.w - m);
    float s = a.x + a.y + a.z + a.w + b.x + b.y + b.z + b.w;
    #pragma unroll
    for (int o = 16; o > 0; o >>= 1) s += __shfl_xor_sync(0xffffffffu, s, o);
    if ((t & 31) == 0) rsm[t >> 5] = s;
    __syncthreads();
    s = 0.f;
    #pragma unroll
    for (int i = 0; i < 8; i++) s += rsm[i];
    float inv = 1.0f / s;
    q[2 * t]           = __floats2half2_rn(a.x * inv, a.y * inv);
    q[2 * t + 1]       = __floats2half2_rn(a.z * inv, a.w * inv);
    q[2 * (t + 256)]     = __floats2half2_rn(b.x * inv, b.y * inv);
    q[2 * (t + 256) + 1] = __floats2half2_rn(b.z * inv, b.w * inv);
}

// ---------------------------------------------------------------------------
// Batched fp16 32x32 transpose: in[z][Rr][Cc] -> out[z][Cc][Rr]
// ---------------------------------------------------------------------------
__global__ __launch_bounds__(256)
void transpose_h(const __half* __restrict__ in, __half* __restrict__ out,
                 int Rr, int Cc)
{
    __shared__ __half t[32][33];
    size_t base = (size_t)blockIdx.z * Rr * Cc;
    int bx = blockIdx.x * 32;
    int by = blockIdx.y * 32;
    int x = threadIdx.x, y = threadIdx.y;  // 32x8
    #pragma unroll
    for (int i = 0; i < 32; i += 8)
        t[y + i][x] = in[base + (size_t)(by + y + i) * Cc + bx + x];
    __syncthreads();
    #pragma unroll
    for (int i = 0; i < 32; i += 8)
        out[base + (size_t)(bx + y + i) * Rr + by + x] = t[x][y + i];
}

// ---------------------------------------------------------------------------
// fp16 mma.sync GEMM:  C[M,N] = A[M,K] @ B[K,N]  (NN, batched via z)
// CTA 128x128x32, 256 threads = 8 warps (2m x 4n), warp tile 64x32.
// 4-stage cp.async pipeline; ldmatrix fragment loads; padded smem rows.
// EPI: 0 none | 1 +bias | 2 +bias+gelu | 3 +bias+residual(fp32) | 4 *alpha
// ---------------------------------------------------------------------------
constexpr int A_STRIDE = 40;    // halves per A smem row (80B, conflict-free ldmatrix)
constexpr int B_STRIDE = 136;   // halves per B smem row (272B)
constexpr int SA_BYTES = 128 * A_STRIDE * 2;            // 10240
constexpr int SB_BYTES = 32 * B_STRIDE * 2;             // 8704
constexpr int STAGE_BYTES = SA_BYTES + SB_BYTES;        // 18944
constexpr int N_STAGE = 4;
constexpr int SM_TOT = N_STAGE * STAGE_BYTES;           // 75776

template<int EPI, typename TO>
__global__ __launch_bounds__(256)
void gemm_h(const __half* __restrict__ A, const __half* __restrict__ Bm,
            const float* __restrict__ bias, const float* __restrict__ res,
            TO* __restrict__ C, int M, int N, int K,
            size_t bA, size_t bB, size_t bC, float alpha)
{
    extern __shared__ char smem[];
    const uint32_t sm0 = smem_u32(smem);
    const int tid = threadIdx.x, lane = tid & 31, wid = tid >> 5;
    const int wm = wid >> 2, wn = wid & 3;
    const int g = lane >> 2, tq = lane & 3;
    const int mb = blockIdx.y * 128, nb = blockIdx.x * 128;

    const __half* Ab = A  + blockIdx.z * bA + (size_t)mb * K;
    const __half* Bb = Bm + blockIdx.z * bB + nb;
    TO*           Cb = C  + blockIdx.z * bC;
    const float*  Rb = (EPI == 3) ? res + blockIdx.z * bC : nullptr;

    // cp.async mappings: A 128 rows x 4 chunks(16B); B 32 k-rows x 16 chunks
    const int ar = tid >> 1, ac = (tid & 1) * 2;
    const int bkr = tid >> 3, bcc = (tid & 7) * 2;
    const uint32_t a_dst = sm0 + (uint32_t)(ar * A_STRIDE + ac * 8) * 2;
    const uint32_t b_dst = sm0 + SA_BYTES + (uint32_t)(bkr * B_STRIDE + bcc * 8) * 2;
    const __half* a_src = Ab + (size_t)ar * K + ac * 8;
    const __half* b_src = Bb + (size_t)bkr * N + bcc * 8;

    auto load = [&](int c, int s) {
        uint32_t ad = a_dst + s * STAGE_BYTES;
        uint32_t bd = b_dst + s * STAGE_BYTES;
        const __half* as = a_src + c * 32;
        const __half* bs = b_src + (size_t)c * 32 * N;
        cpasync16(ad,      as);
        cpasync16(ad + 16, as + 8);
        cpasync16(bd,      bs);
        cpasync16(bd + 16, bs + 8);
        asm volatile("cp.async.commit_group;" ::: "memory");
    };

    // ldmatrix per-lane bases (lane&15 = row / k-row ; lane>>4 = 16B half-select)
    const uint32_t a_frag = sm0 +
        (uint32_t)(((wm * 64 + (lane & 15)) * A_STRIDE + (lane >> 4) * 8) * 2);
    const uint32_t b_frag = sm0 + SA_BYTES +
        (uint32_t)(((lane & 15) * B_STRIDE + wn * 32 + (lane >> 4) * 8) * 2);

    float acc[4][4][4];
    #pragma unroll
    for (int i = 0; i < 4; i++)
        #pragma unroll
        for (int j = 0; j < 4; j++)
            #pragma unroll
            for (int r = 0; r < 4; r++) acc[i][j][r] = 0.f;

    const int NC = K / 32;
    #pragma unroll
    for (int s = 0; s < N_STAGE - 1; s++)
        if (s < NC) load(s, s);

    for (int c = 0; c < NC; c++) {
        int ahead = NC - 1 - c;
        if (ahead >= 2)      asm volatile("cp.async.wait_group 2;" ::: "memory");
        else if (ahead == 1) asm volatile("cp.async.wait_group 1;" ::: "memory");
        else                 asm volatile("cp.async.wait_group 0;" ::: "memory");
        __syncthreads();
        if (c + N_STAGE - 1 < NC) load(c + N_STAGE - 1, (c + N_STAGE - 1) & 3);

        const uint32_t au = a_frag + (c & 3) * STAGE_BYTES;
        const uint32_t bu = b_frag + (c & 3) * STAGE_BYTES;
        #pragma unroll
        for (int ks = 0; ks < 2; ks++) {
            uint32_t af[4][4], bf[2][4];
            #pragma unroll
            for (int i = 0; i < 4; i++)
                ldm_x4(af[i], au + i * (16 * A_STRIDE * 2) + ks * 32);
            ldm_x4_t(bf[0], bu + ks * (16 * B_STRIDE * 2));
            ldm_x4_t(bf[1], bu + ks * (16 * B_STRIDE * 2) + 32);
            #pragma unroll
            for (int i = 0; i < 4; i++)
                #pragma unroll
                for (int j = 0; j < 4; j++)
                    mma16(acc[i][j], af[i], &bf[j >> 1][(j & 1) * 2]);
        }
    }

    // epilogue
    #pragma unroll
    for (int i = 0; i < 4; i++) {
        const int r0 = mb + wm * 64 + i * 16 + g;
        #pragma unroll
        for (int j = 0; j < 4; j++) {
            const int col = nb + wn * 32 + j * 8 + 2 * tq;
            float v0 = acc[i][j][0], v1 = acc[i][j][1];
            float v2 = acc[i][j][2], v3 = acc[i][j][3];
            if (EPI == 4) { v0 *= alpha; v1 *= alpha; v2 *= alpha; v3 *= alpha; }
            if (EPI == 1 || EPI == 2 || EPI == 3) {
                float2 bb = *reinterpret_cast<const float2*>(bias + col);
                v0 += bb.x; v1 += bb.y; v2 += bb.x; v3 += bb.y;
            }
            if (EPI == 2) {
                v0 = 0.5f * v0 * (1.0f + erff(v0 * 0.70710678118654752f));
                v1 = 0.5f * v1 * (1.0f + erff(v1 * 0.70710678118654752f));
                v2 = 0.5f * v2 * (1.0f + erff(v2 * 0.70710678118654752f));
                v3 = 0.5f * v3 * (1.0f + erff(v3 * 0.70710678118654752f));
            }
            if (EPI == 3) {
                float2 r1 = *reinterpret_cast<const float2*>(Rb + (size_t)r0 * N + col);
                float2 r2 = *reinterpret_cast<const float2*>(Rb + (size_t)(r0 + 8) * N + col);
                v0 += r1.x; v1 += r1.y; v2 += r2.x; v3 += r2.y;
            }
            store2(Cb + (size_t)r0 * N + col,       v0, v1);
            store2(Cb + (size_t)(r0 + 8) * N + col, v2, v3);
        }
    }
}

// ---------------------------------------------------------------------------
// Launch graph
// ---------------------------------------------------------------------------
extern "C" void kernel_launch(void* const* d_in, const int* in_sizes, int n_in,
                              void* d_out, int out_size)
{
    (void)in_sizes; (void)n_in; (void)out_size;
    const float* x    = (const float*)d_in[0];
    const float* ln1g = (const float*)d_in[1];
    const float* ln1b = (const float*)d_in[2];
    const float* Wq   = (const float*)d_in[3];
    const float* bq   = (const float*)d_in[4];
    const float* Wk   = (const float*)d_in[5];
    const float* bk   = (const float*)d_in[6];
    const float* Wv   = (const float*)d_in[7];
    const float* bv   = (const float*)d_in[8];
    const float* Wo   = (const float*)d_in[9];
    const float* bo   = (const float*)d_in[10];
    const float* ln2g = (const float*)d_in[11];
    const float* ln2b = (const float*)d_in[12];
    const float* W1   = (const float*)d_in[13];
    const float* b1   = (const float*)d_in[14];
    const float* W2   = (const float*)d_in[15];
    const float* b2   = (const float*)d_in[16];
    float* out = (float*)d_out;

    float *xn, *sc, *y;
    __half *xnh, *qh, *kh, *kth, *vh, *sch, *hoh, *hh, *midh;
    __half *wqh, *wkh, *wvh, *woh, *w1h, *w2h;
    cudaGetSymbolAddress((void**)&xn,   g_xn);
    cudaGetSymbolAddress((void**)&xnh,  g_xnh);
    cudaGetSymbolAddress((void**)&qh,   g_qh);
    cudaGetSymbolAddress((void**)&kh,   g_kh);
    cudaGetSymbolAddress((void**)&kth,  g_kth);
    cudaGetSymbolAddress((void**)&vh,   g_vh);
    cudaGetSymbolAddress((void**)&sc,   g_sc);
    cudaGetSymbolAddress((void**)&sch,  g_sch);
    cudaGetSymbolAddress((void**)&hoh,  g_hoh);
    cudaGetSymbolAddress((void**)&y,    g_y);
    cudaGetSymbolAddress((void**)&hh,   g_hh);
    cudaGetSymbolAddress((void**)&midh, g_midh);
    cudaGetSymbolAddress((void**)&wqh,  g_wqh);
    cudaGetSymbolAddress((void**)&wkh,  g_wkh);
    cudaGetSymbolAddress((void**)&wvh,  g_wvh);
    cudaGetSymbolAddress((void**)&woh,  g_woh);
    cudaGetSymbolAddress((void**)&w1h,  g_w1h);
    cudaGetSymbolAddress((void**)&w2h,  g_w2h);

    cudaFuncSetAttribute(gemm_h<0, __half>, cudaFuncAttributeMaxDynamicSharedMemorySize, SM_TOT);
    cudaFuncSetAttribute(gemm_h<1, __half>, cudaFuncAttributeMaxDynamicSharedMemorySize, SM_TOT);
    cudaFuncSetAttribute(gemm_h<2, __half>, cudaFuncAttributeMaxDynamicSharedMemorySize, SM_TOT);
    cudaFuncSetAttribute(gemm_h<3, float>,  cudaFuncAttributeMaxDynamicSharedMemorySize, SM_TOT);
    cudaFuncSetAttribute(gemm_h<4, float>,  cudaFuncAttributeMaxDynamicSharedMemorySize, SM_TOT);

    const float scale = 0.08838834764831845f;  // 1/sqrt(128)

    // 0. convert weights to fp16
    f2h_kernel<<<(D_ * DK_ / 4 + 255) / 256, 256>>>(Wq, wqh, D_ * DK_ / 4);
    f2h_kernel<<<(D_ * DK_ / 4 + 255) / 256, 256>>>(Wk, wkh, D_ * DK_ / 4);
    f2h_kernel<<<(D_ * DK_ / 4 + 255) / 256, 256>>>(Wv, wvh, D_ * DK_ / 4);
    f2h_kernel<<<(DK_ * D_ / 4 + 255) / 256, 256>>>(Wo, woh, DK_ * D_ / 4);
    f2h_kernel<<<(D_ * H_ / 4 + 255) / 256, 256>>>(W1, w1h, D_ * H_ / 4);
    f2h_kernel<<<(H_ * D_ / 4 + 255) / 256, 256>>>(W2, w2h, H_ * D_ / 4);

    // 1. xn = LN1(x)  (fp32 + fp16)
    ln_kernel<true, true><<<R_, 256>>>(x, ln1g, ln1b, xn, xnh);

    // 2-4. q/k/v = xnh @ W{q,k,v} + b  -> fp16
    gemm_h<1, __half><<<dim3(1, 128, 1), 256, SM_TOT>>>(xnh, wqh, bq, nullptr, qh, R_, DK_, D_, 0, 0, 0, 0.f);
    gemm_h<1, __half><<<dim3(1, 128, 1), 256, SM_TOT>>>(xnh, wkh, bk, nullptr, kh, R_, DK_, D_, 0, 0, 0, 0.f);
    gemm_h<1, __half><<<dim3(1, 128, 1), 256, SM_TOT>>>(xnh, wvh, bv, nullptr, vh, R_, DK_, D_, 0, 0, 0, 0.f);

    // 4b. kt[b] = k[b]^T
    transpose_h<<<dim3(DK_ / 32, S_ / 32, B_), dim3(32, 8)>>>(kh, kth, S_, DK_);

    // 5. sc[b] = q[b] @ kt[b] * scale   -> fp32
    gemm_h<4, float><<<dim3(16, 16, B_), 256, SM_TOT>>>(
        qh, kth, nullptr, nullptr, sc, S_, S_, DK_,
        (size_t)S_ * DK_, (size_t)DK_ * S_, (size_t)S_ * S_, scale);

    // 6. softmax rows (fp32 -> fp16 probs)
    softmax_kernel<<<R_, 256>>>(sc, sch);

    // 7. ho[b] = probs[b] @ v[b]   -> fp16
    gemm_h<0, __half><<<dim3(1, 16, B_), 256, SM_TOT>>>(
        sch, vh, nullptr, nullptr, hoh, S_, DK_, S_,
        (size_t)S_ * S_, (size_t)S_ * DK_, (size_t)S_ * DK_, 0.f);

    // 8. y = xn + ho @ Wo + bo  -> fp32
    gemm_h<3, float><<<dim3(8, 128, 1), 256, SM_TOT>>>(hoh, woh, bo, xn, y, R_, D_, DK_, 0, 0, 0, 0.f);

    // 9. h = LN2(y) -> fp16
    ln_kernel<false, true><<<R_, 256>>>(y, ln2g, ln2b, nullptr, hh);

    // 10. mid = gelu(h @ W1 + b1)  -> fp16
    gemm_h<2, __half><<<dim3(32, 128, 1), 256, SM_TOT>>>(hh, w1h, b1, nullptr, midh, R_, H_, D_, 0, 0, 0, 0.f);

    // 11. out = y + mid @ W2 + b2  -> fp32
    gemm_h<3, float><<<dim3(8, 128, 1), 256, SM_TOT>>>(midh, w2h, b2, y, out, R_, D_, H_, 0, 0, 0, 0.f);
}

// round 8
// speedup vs baseline: 5.5011x; 1.0334x over previous
#include <cuda_runtime.h>
#include <cuda_fp16.h>
#include <math.h>
#include <stdint.h>

// Problem shape (fixed by the dataset)
constexpr int B_  = 8;
constexpr int S_  = 2048;
constexpr int D_  = 1024;
constexpr int DK_ = 128;   // == DV
constexpr int H_  = 4096;  // 4*D
constexpr int R_  = B_ * S_;   // 16384 rows

// ---------------------------------------------------------------------------
// Scratch (device globals -- no dynamic allocation allowed)
// ---------------------------------------------------------------------------
__device__ float  g_xn [R_ * D_];              // fp32 ln1(x)  (residual source)
__device__ __half g_xnh[R_ * D_];              // fp16 ln1(x)  (GEMM A)
__device__ __half g_qh [R_ * DK_];
__device__ __half g_kh [R_ * DK_];
__device__ __half g_vh [R_ * DK_];
__device__ __half g_hoh[R_ * DK_];             // fp16 attention output
__device__ float  g_y  [R_ * D_];              // fp32 post-attn residual
__device__ __half g_hh [R_ * D_];              // fp16 ln2(y)
__device__ __half g_midh[(size_t)R_ * H_];     // fp16 MLP hidden
// fp16 weights
__device__ __half g_wqh[D_ * DK_];
__device__ __half g_wkh[D_ * DK_];
__device__ __half g_wvh[D_ * DK_];
__device__ __half g_woh[DK_ * D_];
__device__ __half g_w1h[(size_t)D_ * H_];
__device__ __half g_w2h[(size_t)H_ * D_];

// ---------------------------------------------------------------------------
// helpers
// ---------------------------------------------------------------------------
__device__ __forceinline__ uint32_t smem_u32(const void* p) {
    uint32_t a;
    asm("{ .reg .u64 t; cvta.to.shared.u64 t, %1; cvt.u32.u64 %0, t; }"
        : "=r"(a) : "l"(p));
    return a;
}
__device__ __forceinline__ void cpasync16(uint32_t dst, const void* src) {
    asm volatile("cp.async.cg.shared.global [%0], [%1], 16;" :: "r"(dst), "l"(src));
}
__device__ __forceinline__ void ldm_x4(uint32_t* r, uint32_t addr) {
    asm volatile("ldmatrix.sync.aligned.m8n8.x4.shared.b16 {%0,%1,%2,%3}, [%4];"
        : "=r"(r[0]), "=r"(r[1]), "=r"(r[2]), "=r"(r[3]) : "r"(addr));
}
__device__ __forceinline__ void ldm_x4_t(uint32_t* r, uint32_t addr) {
    asm volatile("ldmatrix.sync.aligned.m8n8.x4.trans.shared.b16 {%0,%1,%2,%3}, [%4];"
        : "=r"(r[0]), "=r"(r[1]), "=r"(r[2]), "=r"(r[3]) : "r"(addr));
}
__device__ __forceinline__ void mma16(float* c, const uint32_t* a, const uint32_t* b) {
    asm volatile(
        "mma.sync.aligned.m16n8k16.row.col.f32.f16.f16.f32 "
        "{%0,%1,%2,%3},{%4,%5,%6,%7},{%8,%9},{%0,%1,%2,%3};"
        : "+f"(c[0]), "+f"(c[1]), "+f"(c[2]), "+f"(c[3])
        : "r"(a[0]), "r"(a[1]), "r"(a[2]), "r"(a[3]), "r"(b[0]), "r"(b[1]));
}
__device__ __forceinline__ void store2(float* p, float a, float b) {
    *reinterpret_cast<float2*>(p) = make_float2(a, b);
}
__device__ __forceinline__ void store2(__half* p, float a, float b) {
    *reinterpret_cast<__half2*>(p) = __floats2half2_rn(a, b);
}
__device__ __forceinline__ uint32_t packh2(float a, float b) {
    __half2 h = __floats2half2_rn(a, b);
    return *reinterpret_cast<uint32_t*>(&h);
}

// ---------------------------------------------------------------------------
// fp32 -> fp16 elementwise (n % 4 == 0)
// ---------------------------------------------------------------------------
__global__ __launch_bounds__(256)
void f2h_kernel(const float* __restrict__ in, __half* __restrict__ out, int n4)
{
    int i = blockIdx.x * blockDim.x + threadIdx.x;
    if (i < n4) {
        float4 v = reinterpret_cast<const float4*>(in)[i];
        reinterpret_cast<__half2*>(out)[2 * i]     = __floats2half2_rn(v.x, v.y);
        reinterpret_cast<__half2*>(out)[2 * i + 1] = __floats2half2_rn(v.z, v.w);
    }
}

// ---------------------------------------------------------------------------
// LayerNorm: one block per row, D=1024 -> 256 threads x float4
// ---------------------------------------------------------------------------
template<bool W32, bool W16>
__global__ __launch_bounds__(256)
void ln_kernel(const float* __restrict__ x, const float* __restrict__ g,
               const float* __restrict__ b, float* __restrict__ out32,
               __half* __restrict__ out16)
{
    int row = blockIdx.x;
    int t = threadIdx.x;
    float4 v = reinterpret_cast<const float4*>(x + (size_t)row * D_)[t];
    float s  = v.x + v.y + v.z + v.w;
    float ss = v.x*v.x + v.y*v.y + v.z*v.z + v.w*v.w;
    #pragma unroll
    for (int o = 16; o > 0; o >>= 1) {
        s  += __shfl_xor_sync(0xffffffffu, s,  o);
        ss += __shfl_xor_sync(0xffffffffu, ss, o);
    }
    __shared__ float rs[8], rss[8];
    if ((t & 31) == 0) { rs[t >> 5] = s; rss[t >> 5] = ss; }
    __syncthreads();
    float sum = 0.f, sumsq = 0.f;
    #pragma unroll
    for (int i = 0; i < 8; i++) { sum += rs[i]; sumsq += rss[i]; }
    float mu   = sum * (1.0f / D_);
    float var  = sumsq * (1.0f / D_) - mu * mu;
    float rstd = rsqrtf(var + 1e-5f);
    float4 gg = reinterpret_cast<const float4*>(g)[t];
    float4 bb = reinterpret_cast<const float4*>(b)[t];
    float4 o;
    o.x = (v.x - mu) * rstd * gg.x + bb.x;
    o.y = (v.y - mu) * rstd * gg.y + bb.y;
    o.z = (v.z - mu) * rstd * gg.z + bb.z;
    o.w = (v.w - mu) * rstd * gg.w + bb.w;
    if (W32)
        reinterpret_cast<float4*>(out32 + (size_t)row * D_)[t] = o;
    if (W16) {
        __half2* p = reinterpret_cast<__half2*>(out16 + (size_t)row * D_);
        p[2 * t]     = __floats2half2_rn(o.x, o.y);
        p[2 * t + 1] = __floats2half2_rn(o.z, o.w);
    }
}

// ---------------------------------------------------------------------------
// Flash attention forward: ho = softmax(q k^T / sqrt(DK)) v  (per batch)
// grid (S/128, B); 256 threads = 8 warps x 16 q-rows; K/V blocks of 128,
// double-buffered cp.async; online softmax; P kept in registers.
// ---------------------------------------------------------------------------
constexpr int FA_STRIDE = 136;                    // halves per smem row (272 B)
constexpr int FA_TILE   = 128 * FA_STRIDE * 2;    // 34816 B
constexpr int FA_SMEM   = 5 * FA_TILE;            // Q + 2*(K,V) = 174080 B
constexpr int FA_NB     = S_ / 128;               // 16

__global__ __launch_bounds__(256, 1)
void flash_kernel(const __half* __restrict__ q, const __half* __restrict__ k,
                  const __half* __restrict__ v, __half* __restrict__ o,
                  float scale)
{
    extern __shared__ char smem[];
    const uint32_t smQ  = smem_u32(smem);
    const uint32_t smKV = smQ + FA_TILE;          // [buf][K|V]
    const int tid = threadIdx.x, lane = tid & 31, wid = tid >> 5;
    const int g = lane >> 2, tq = lane & 3;
    const int batch = blockIdx.y, qblk = blockIdx.x;

    const __half* Qg = q + ((size_t)batch * S_ + qblk * 128) * DK_;
    const __half* Kg = k + (size_t)batch * S_ * DK_;
    const __half* Vg = v + (size_t)batch * S_ * DK_;

    // tile loader: 256 threads x 128B
    const int lr = tid >> 1, lc = (tid & 1) * 64;
    const uint32_t ldst = (uint32_t)(lr * FA_STRIDE + lc) * 2;
    auto load_tile = [&](uint32_t smbase, const __half* src) {
        const __half* s = src + (size_t)lr * DK_ + lc;
        #pragma unroll
        for (int i = 0; i < 8; i++)
            cpasync16(smbase + ldst + i * 16, s + i * 8);
    };

    load_tile(smQ, Qg);
    load_tile(smKV, Kg);
    load_tile(smKV + FA_TILE, Vg);
    asm volatile("cp.async.commit_group;" ::: "memory");

    float o_acc[16][4];
    #pragma unroll
    for (int i = 0; i < 16; i++)
        #pragma unroll
        for (int r = 0; r < 4; r++) o_acc[i][r] = 0.f;
    float m0 = -INFINITY, m1 = -INFINITY, l0 = 0.f, l1 = 0.f;

    const uint32_t aQ = smQ +
        (uint32_t)(((wid * 16 + (lane & 15)) * FA_STRIDE + (lane >> 4) * 8) * 2);
    const uint32_t fragoff =
        (uint32_t)(((lane & 15) * FA_STRIDE + (lane >> 4) * 8) * 2);

    for (int j = 0; j < FA_NB; j++) {
        const uint32_t smK = smKV + (j & 1) * 2 * FA_TILE;
        const uint32_t smV = smK + FA_TILE;
        __syncthreads();   // everyone done reading the buffer we overwrite next
        if (j + 1 < FA_NB) {
            const uint32_t nK = smKV + ((j + 1) & 1) * 2 * FA_TILE;
            load_tile(nK, Kg + (size_t)(j + 1) * 128 * DK_);
            load_tile(nK + FA_TILE, Vg + (size_t)(j + 1) * 128 * DK_);
            asm volatile("cp.async.commit_group;" ::: "memory");
            asm volatile("cp.async.wait_group 1;" ::: "memory");
        } else {
            asm volatile("cp.async.wait_group 0;" ::: "memory");
        }
        __syncthreads();

        // ---- S = Q @ K^T  (warp: 16 q-rows x 128 keys) ----
        float sca[16][4];
        #pragma unroll
        for (int i = 0; i < 16; i++)
            #pragma unroll
            for (int r = 0; r < 4; r++) sca[i][r] = 0.f;
        const uint32_t bK = smK + fragoff;
        #pragma unroll
        for (int dc = 0; dc < 8; dc++) {
            uint32_t af[4];
            ldm_x4(af, aQ + dc * 32);
            #pragma unroll
            for (int kb = 0; kb < 8; kb++) {
                uint32_t bf[4];
                ldm_x4(bf, bK + (uint32_t)((kb * 16 * FA_STRIDE + dc * 16) * 2));
                uint32_t b0[2] = { bf[0], bf[2] };
                uint32_t b1[2] = { bf[1], bf[3] };
                mma16(sca[2 * kb],     af, b0);
                mma16(sca[2 * kb + 1], af, b1);
            }
        }

        // ---- online softmax ----
        float mr0 = -INFINITY, mr1 = -INFINITY;
        #pragma unroll
        for (int jb = 0; jb < 16; jb++) {
            mr0 = fmaxf(mr0, fmaxf(sca[jb][0], sca[jb][1]));
            mr1 = fmaxf(mr1, fmaxf(sca[jb][2], sca[jb][3]));
        }
        mr0 = fmaxf(mr0, __shfl_xor_sync(0xffffffffu, mr0, 1));
        mr0 = fmaxf(mr0, __shfl_xor_sync(0xffffffffu, mr0, 2));
        mr1 = fmaxf(mr1, __shfl_xor_sync(0xffffffffu, mr1, 1));
        mr1 = fmaxf(mr1, __shfl_xor_sync(0xffffffffu, mr1, 2));
        float mn0 = fmaxf(m0, mr0 * scale);
        float mn1 = fmaxf(m1, mr1 * scale);
        float c0 = __expf(m0 - mn0);
        float c1 = __expf(m1 - mn1);
        m0 = mn0; m1 = mn1;
        #pragma unroll
        for (int jb = 0; jb < 16; jb++) {
            o_acc[jb][0] *= c0; o_acc[jb][1] *= c0;
            o_acc[jb][2] *= c1; o_acc[jb][3] *= c1;
        }
        float ps0 = 0.f, ps1 = 0.f;
        uint32_t ph[16][2];
        #pragma unroll
        for (int jb = 0; jb < 16; jb++) {
            float p0 = __expf(sca[jb][0] * scale - mn0);
            float p1 = __expf(sca[jb][1] * scale - mn0);
            float p2 = __expf(sca[jb][2] * scale - mn1);
            float p3 = __expf(sca[jb][3] * scale - mn1);
            ps0 += p0 + p1; ps1 += p2 + p3;
            ph[jb][0] = packh2(p0, p1);
            ph[jb][1] = packh2(p2, p3);
        }
        ps0 += __shfl_xor_sync(0xffffffffu, ps0, 1);
        ps0 += __shfl_xor_sync(0xffffffffu, ps0, 2);
        ps1 += __shfl_xor_sync(0xffffffffu, ps1, 1);
        ps1 += __shfl_xor_sync(0xffffffffu, ps1, 2);
        l0 = l0 * c0 + ps0;
        l1 = l1 * c1 + ps1;

        // ---- O += P @ V ----
        const uint32_t bV = smV + fragoff;
        #pragma unroll
        for (int j2 = 0; j2 < 8; j2++) {
            uint32_t paf[4] = { ph[2 * j2][0], ph[2 * j2][1],
                                ph[2 * j2 + 1][0], ph[2 * j2 + 1][1] };
            #pragma unroll
            for (int db = 0; db < 8; db++) {
                uint32_t bf[4];
                ldm_x4_t(bf, bV + (uint32_t)((j2 * 16 * FA_STRIDE + db * 16) * 2));
                mma16(o_acc[2 * db],     paf, bf);
                mma16(o_acc[2 * db + 1], paf, bf + 2);
            }
        }
    }

    // ---- epilogue ----
    const float i0 = 1.f / l0, i1 = 1.f / l1;
    const int row0 = qblk * 128 + wid * 16 + g;
    __half* O0 = o + ((size_t)batch * S_ + row0) * DK_;
    #pragma unroll
    for (int jb = 0; jb < 16; jb++) {
        const int d = jb * 8 + 2 * tq;
        store2(O0 + d,            o_acc[jb][0] * i0, o_acc[jb][1] * i0);
        store2(O0 + 8 * DK_ + d,  o_acc[jb][2] * i1, o_acc[jb][3] * i1);
    }
}

// ---------------------------------------------------------------------------
// fp16 mma.sync GEMM:  C[M,N] = A[M,K] @ B[K,N]  (NN, batched via z)
// CTA 128x128x32, 256 threads = 8 warps (2m x 4n), warp tile 64x32.
// 4-stage cp.async pipeline; ldmatrix fragment loads; padded smem rows.
// EPI: 0 none | 1 +bias | 2 +bias+gelu | 3 +bias+residual(fp32)
// ---------------------------------------------------------------------------
constexpr int A_STRIDE = 40;
constexpr int B_STRIDE = 136;
constexpr int SA_BYTES = 128 * A_STRIDE * 2;            // 10240
constexpr int SB_BYTES = 32 * B_STRIDE * 2;             // 8704
constexpr int STAGE_BYTES = SA_BYTES + SB_BYTES;        // 18944
constexpr int N_STAGE = 4;
constexpr int SM_TOT = N_STAGE * STAGE_BYTES;           // 75776

template<int EPI, typename TO>
__global__ __launch_bounds__(256)
void gemm_h(const __half* __restrict__ A, const __half* __restrict__ Bm,
            const float* __restrict__ bias, const float* __restrict__ res,
            TO* __restrict__ C, int M, int N, int K,
            size_t bA, size_t bB, size_t bC)
{
    extern __shared__ char smem[];
    const uint32_t sm0 = smem_u32(smem);
    const int tid = threadIdx.x, lane = tid & 31, wid = tid >> 5;
    const int wm = wid >> 2, wn = wid & 3;
    const int g = lane >> 2, tq = lane & 3;
    const int mb = blockIdx.y * 128, nb = blockIdx.x * 128;

    const __half* Ab = A  + blockIdx.z * bA + (size_t)mb * K;
    const __half* Bb = Bm + blockIdx.z * bB + nb;
    TO*           Cb = C  + blockIdx.z * bC;
    const float*  Rb = (EPI == 3) ? res + blockIdx.z * bC : nullptr;

    const int ar = tid >> 1, ac = (tid & 1) * 2;
    const int bkr = tid >> 3, bcc = (tid & 7) * 2;
    const uint32_t a_dst = sm0 + (uint32_t)(ar * A_STRIDE + ac * 8) * 2;
    const uint32_t b_dst = sm0 + SA_BYTES + (uint32_t)(bkr * B_STRIDE + bcc * 8) * 2;
    const __half* a_src = Ab + (size_t)ar * K + ac * 8;
    const __half* b_src = Bb + (size_t)bkr * N + bcc * 8;

    auto load = [&](int c, int s) {
        uint32_t ad = a_dst + s * STAGE_BYTES;
        uint32_t bd = b_dst + s * STAGE_BYTES;
        const __half* as = a_src + c * 32;
        const __half* bs = b_src + (size_t)c * 32 * N;
        cpasync16(ad,      as);
        cpasync16(ad + 16, as + 8);
        cpasync16(bd,      bs);
        cpasync16(bd + 16, bs + 8);
        asm volatile("cp.async.commit_group;" ::: "memory");
    };

    const uint32_t a_frag = sm0 +
        (uint32_t)(((wm * 64 + (lane & 15)) * A_STRIDE + (lane >> 4) * 8) * 2);
    const uint32_t b_frag = sm0 + SA_BYTES +
        (uint32_t)(((lane & 15) * B_STRIDE + wn * 32 + (lane >> 4) * 8) * 2);

    float acc[4][4][4];
    #pragma unroll
    for (int i = 0; i < 4; i++)
        #pragma unroll
        for (int j = 0; j < 4; j++)
            #pragma unroll
            for (int r = 0; r < 4; r++) acc[i][j][r] = 0.f;

    const int NC = K / 32;
    #pragma unroll
    for (int s = 0; s < N_STAGE - 1; s++)
        if (s < NC) load(s, s);

    for (int c = 0; c < NC; c++) {
        int ahead = NC - 1 - c;
        if (ahead >= 2)      asm volatile("cp.async.wait_group 2;" ::: "memory");
        else if (ahead == 1) asm volatile("cp.async.wait_group 1;" ::: "memory");
        else                 asm volatile("cp.async.wait_group 0;" ::: "memory");
        __syncthreads();
        if (c + N_STAGE - 1 < NC) load(c + N_STAGE - 1, (c + N_STAGE - 1) & 3);

        const uint32_t au = a_frag + (c & 3) * STAGE_BYTES;
        const uint32_t bu = b_frag + (c & 3) * STAGE_BYTES;
        #pragma unroll
        for (int ks = 0; ks < 2; ks++) {
            uint32_t af[4][4], bf[2][4];
            #pragma unroll
            for (int i = 0; i < 4; i++)
                ldm_x4(af[i], au + i * (16 * A_STRIDE * 2) + ks * 32);
            ldm_x4_t(bf[0], bu + ks * (16 * B_STRIDE * 2));
            ldm_x4_t(bf[1], bu + ks * (16 * B_STRIDE * 2) + 32);
            #pragma unroll
            for (int i = 0; i < 4; i++)
                #pragma unroll
                for (int j = 0; j < 4; j++)
                    mma16(acc[i][j], af[i], &bf[j >> 1][(j & 1) * 2]);
        }
    }

    #pragma unroll
    for (int i = 0; i < 4; i++) {
        const int r0 = mb + wm * 64 + i * 16 + g;
        #pragma unroll
        for (int j = 0; j < 4; j++) {
            const int col = nb + wn * 32 + j * 8 + 2 * tq;
            float v0 = acc[i][j][0], v1 = acc[i][j][1];
            float v2 = acc[i][j][2], v3 = acc[i][j][3];
            if (EPI == 1 || EPI == 2 || EPI == 3) {
                float2 bb = *reinterpret_cast<const float2*>(bias + col);
                v0 += bb.x; v1 += bb.y; v2 += bb.x; v3 += bb.y;
            }
            if (EPI == 2) {
                v0 = 0.5f * v0 * (1.0f + erff(v0 * 0.70710678118654752f));
                v1 = 0.5f * v1 * (1.0f + erff(v1 * 0.70710678118654752f));
                v2 = 0.5f * v2 * (1.0f + erff(v2 * 0.70710678118654752f));
                v3 = 0.5f * v3 * (1.0f + erff(v3 * 0.70710678118654752f));
            }
            if (EPI == 3) {
                float2 r1 = *reinterpret_cast<const float2*>(Rb + (size_t)r0 * N + col);
                float2 r2 = *reinterpret_cast<const float2*>(Rb + (size_t)(r0 + 8) * N + col);
                v0 += r1.x; v1 += r1.y; v2 += r2.x; v3 += r2.y;
            }
            store2(Cb + (size_t)r0 * N + col,       v0, v1);
            store2(Cb + (size_t)(r0 + 8) * N + col, v2, v3);
        }
    }
}

// ---------------------------------------------------------------------------
// Launch graph
// ---------------------------------------------------------------------------
extern "C" void kernel_launch(void* const* d_in, const int* in_sizes, int n_in,
                              void* d_out, int out_size)
{
    (void)in_sizes; (void)n_in; (void)out_size;
    const float* x    = (const float*)d_in[0];
    const float* ln1g = (const float*)d_in[1];
    const float* ln1b = (const float*)d_in[2];
    const float* Wq   = (const float*)d_in[3];
    const float* bq   = (const float*)d_in[4];
    const float* Wk   = (const float*)d_in[5];
    const float* bk   = (const float*)d_in[6];
    const float* Wv   = (const float*)d_in[7];
    const float* bv   = (const float*)d_in[8];
    const float* Wo   = (const float*)d_in[9];
    const float* bo   = (const float*)d_in[10];
    const float* ln2g = (const float*)d_in[11];
    const float* ln2b = (const float*)d_in[12];
    const float* W1   = (const float*)d_in[13];
    const float* b1   = (const float*)d_in[14];
    const float* W2   = (const float*)d_in[15];
    const float* b2   = (const float*)d_in[16];
    float* out = (float*)d_out;

    float *xn, *y;
    __half *xnh, *qh, *kh, *vh, *hoh, *hh, *midh;
    __half *wqh, *wkh, *wvh, *woh, *w1h, *w2h;
    cudaGetSymbolAddress((void**)&xn,   g_xn);
    cudaGetSymbolAddress((void**)&xnh,  g_xnh);
    cudaGetSymbolAddress((void**)&qh,   g_qh);
    cudaGetSymbolAddress((void**)&kh,   g_kh);
    cudaGetSymbolAddress((void**)&vh,   g_vh);
    cudaGetSymbolAddress((void**)&hoh,  g_hoh);
    cudaGetSymbolAddress((void**)&y,    g_y);
    cudaGetSymbolAddress((void**)&hh,   g_hh);
    cudaGetSymbolAddress((void**)&midh, g_midh);
    cudaGetSymbolAddress((void**)&wqh,  g_wqh);
    cudaGetSymbolAddress((void**)&wkh,  g_wkh);
    cudaGetSymbolAddress((void**)&wvh,  g_wvh);
    cudaGetSymbolAddress((void**)&woh,  g_woh);
    cudaGetSymbolAddress((void**)&w1h,  g_w1h);
    cudaGetSymbolAddress((void**)&w2h,  g_w2h);

    cudaFuncSetAttribute(gemm_h<0, __half>, cudaFuncAttributeMaxDynamicSharedMemorySize, SM_TOT);
    cudaFuncSetAttribute(gemm_h<1, __half>, cudaFuncAttributeMaxDynamicSharedMemorySize, SM_TOT);
    cudaFuncSetAttribute(gemm_h<2, __half>, cudaFuncAttributeMaxDynamicSharedMemorySize, SM_TOT);
    cudaFuncSetAttribute(gemm_h<3, float>,  cudaFuncAttributeMaxDynamicSharedMemorySize, SM_TOT);
    cudaFuncSetAttribute(flash_kernel, cudaFuncAttributeMaxDynamicSharedMemorySize, FA_SMEM);

    const float scale = 0.08838834764831845f;  // 1/sqrt(128)

    // 0. convert weights to fp16
    f2h_kernel<<<(D_ * DK_ / 4 + 255) / 256, 256>>>(Wq, wqh, D_ * DK_ / 4);
    f2h_kernel<<<(D_ * DK_ / 4 + 255) / 256, 256>>>(Wk, wkh, D_ * DK_ / 4);
    f2h_kernel<<<(D_ * DK_ / 4 + 255) / 256, 256>>>(Wv, wvh, D_ * DK_ / 4);
    f2h_kernel<<<(DK_ * D_ / 4 + 255) / 256, 256>>>(Wo, woh, DK_ * D_ / 4);
    f2h_kernel<<<(D_ * H_ / 4 + 255) / 256, 256>>>(W1, w1h, D_ * H_ / 4);
    f2h_kernel<<<(H_ * D_ / 4 + 255) / 256, 256>>>(W2, w2h, H_ * D_ / 4);

    // 1. xn = LN1(x)  (fp32 + fp16)
    ln_kernel<true, true><<<R_, 256>>>(x, ln1g, ln1b, xn, xnh);

    // 2-4. q/k/v = xnh @ W{q,k,v} + b  -> fp16
    gemm_h<1, __half><<<dim3(1, 128, 1), 256, SM_TOT>>>(xnh, wqh, bq, nullptr, qh, R_, DK_, D_, 0, 0, 0);
    gemm_h<1, __half><<<dim3(1, 128, 1), 256, SM_TOT>>>(xnh, wkh, bk, nullptr, kh, R_, DK_, D_, 0, 0, 0);
    gemm_h<1, __half><<<dim3(1, 128, 1), 256, SM_TOT>>>(xnh, wvh, bv, nullptr, vh, R_, DK_, D_, 0, 0, 0);

    // 5-7. flash attention: ho = softmax(q k^T * scale) v  -> fp16
    flash_kernel<<<dim3(S_ / 128, B_), 256, FA_SMEM>>>(qh, kh, vh, hoh, scale);

    // 8. y = xn + ho @ Wo + bo  -> fp32
    gemm_h<3, float><<<dim3(8, 128, 1), 256, SM_TOT>>>(hoh, woh, bo, xn, y, R_, D_, DK_, 0, 0, 0);

    // 9. h = LN2(y) -> fp16
    ln_kernel<false, true><<<R_, 256>>>(y, ln2g, ln2b, nullptr, hh);

    // 10. mid = gelu(h @ W1 + b1)  -> fp16
    gemm_h<2, __half><<<dim3(32, 128, 1), 256, SM_TOT>>>(hh, w1h, b1, nullptr, midh, R_, H_, D_, 0, 0, 0);

    // 11. out = y + mid @ W2 + b2  -> fp32
    gemm_h<3, float><<<dim3(8, 128, 1), 256, SM_TOT>>>(midh, w2h, b2, y, out, R_, D_, H_, 0, 0, 0);
}